// round 2
// baseline (speedup 1.0000x reference)
#include <cuda_runtime.h>
#include <cuda_bf16.h>
#include <stdint.h>

#define Bb 4
#define Nn 2048
#define Mm 2048
#define Cc 512
#define Hh 8
#define DHd 64

// ---------------- static scratch (no allocations allowed) ----------------
__device__ __nv_bfloat16 g_qhi[Bb*Hh*Nn*DHd];
__device__ __nv_bfloat16 g_qlo[Bb*Hh*Nn*DHd];
__device__ __nv_bfloat16 g_khi[Bb*Hh*Mm*DHd];
__device__ __nv_bfloat16 g_klo[Bb*Hh*Mm*DHd];
__device__ __nv_bfloat16 g_vhi[Bb*Hh*Mm*DHd];
__device__ __nv_bfloat16 g_vlo[Bb*Hh*Mm*DHd];
__device__ float        g_inv[Bb*Hh*Nn];

// ---------------- helpers ----------------
__device__ __forceinline__ void mma_bf16(float c[4], const uint32_t a[4], const uint32_t b[2]) {
    asm volatile(
        "mma.sync.aligned.m16n8k16.row.col.f32.bf16.bf16.f32 "
        "{%0,%1,%2,%3}, {%4,%5,%6,%7}, {%8,%9}, {%0,%1,%2,%3};\n"
        : "+f"(c[0]), "+f"(c[1]), "+f"(c[2]), "+f"(c[3])
        : "r"(a[0]), "r"(a[1]), "r"(a[2]), "r"(a[3]), "r"(b[0]), "r"(b[1]));
}

__device__ __forceinline__ void split2(float x, __nv_bfloat16 &hi, __nv_bfloat16 &lo) {
    hi = __float2bfloat16_rn(x);
    lo = __float2bfloat16_rn(x - __bfloat162float(hi));
}

__device__ __forceinline__ uint32_t pk2(__nv_bfloat16 a, __nv_bfloat16 b) {
    return (uint32_t)__bfloat16_as_ushort(a) | ((uint32_t)__bfloat16_as_ushort(b) << 16);
}

// ---------------- K1: fused projections (X@W + b), bf16-split mma ----------------
// grid: (64, 8, 3)  block: 256
// z selects q/k/v. CTA tile 128 rows x 64 cols (= exactly one head's 64 dims).
__global__ __launch_bounds__(256) void proj_kernel(
    const float* __restrict__ xq, const float* __restrict__ xk, const float* __restrict__ xv,
    const float* __restrict__ Wq, const float* __restrict__ bq,
    const float* __restrict__ Wk, const float* __restrict__ bk,
    const float* __restrict__ Wv, const float* __restrict__ bv)
{
    const float* X; const float* W; const float* bias;
    __nv_bfloat16 *Ohi, *Olo; float scale;
    int z = blockIdx.z;
    if (z == 0)      { X = xq; W = Wq; bias = bq; Ohi = g_qhi; Olo = g_qlo; scale = 0.125f; } // fold 1/sqrt(64)
    else if (z == 1) { X = xk; W = Wk; bias = bk; Ohi = g_khi; Olo = g_klo; scale = 1.0f; }
    else             { X = xv; W = Wv; bias = bv; Ohi = g_vhi; Olo = g_vlo; scale = 1.0f; }

    __shared__ __nv_bfloat16 Ahi[128][40], Alo[128][40];   // [row][k], k-chunk 32, pad 8
    __shared__ __nv_bfloat16 Bshi[64][40], Bslo[64][40];   // [col][k] transposed

    int tid = threadIdx.x, lane = tid & 31, warp = tid >> 5;
    int row0 = blockIdx.x * 128;
    int col0 = blockIdx.y * 64;
    int wr = (warp >> 1) * 32, wc = (warp & 1) * 32;
    int qr = lane >> 2, qc2 = (lane & 3) * 2;

    float acc[2][4][4];
#pragma unroll
    for (int m = 0; m < 2; m++)
#pragma unroll
        for (int n = 0; n < 4; n++)
#pragma unroll
            for (int e = 0; e < 4; e++) acc[m][n][e] = 0.0f;

    for (int kc = 0; kc < Cc; kc += 32) {
        // load A chunk 128x32
#pragma unroll
        for (int i = tid; i < 128*8; i += 256) {
            int r = i >> 3, c4 = (i & 7) * 4;
            float4 v = *(const float4*)&X[(size_t)(row0 + r)*Cc + kc + c4];
            __nv_bfloat16 h, l;
            split2(v.x, h, l); Ahi[r][c4+0] = h; Alo[r][c4+0] = l;
            split2(v.y, h, l); Ahi[r][c4+1] = h; Alo[r][c4+1] = l;
            split2(v.z, h, l); Ahi[r][c4+2] = h; Alo[r][c4+2] = l;
            split2(v.w, h, l); Ahi[r][c4+3] = h; Alo[r][c4+3] = l;
        }
        // load B chunk 32x64, transposed into [c][k]
#pragma unroll
        for (int i = tid; i < 32*16; i += 256) {
            int kk = i >> 4, c4 = (i & 15) * 4;
            float4 v = *(const float4*)&W[(size_t)(kc + kk)*Cc + col0 + c4];
            __nv_bfloat16 h, l;
            split2(v.x, h, l); Bshi[c4+0][kk] = h; Bslo[c4+0][kk] = l;
            split2(v.y, h, l); Bshi[c4+1][kk] = h; Bslo[c4+1][kk] = l;
            split2(v.z, h, l); Bshi[c4+2][kk] = h; Bslo[c4+2][kk] = l;
            split2(v.w, h, l); Bshi[c4+3][kk] = h; Bslo[c4+3][kk] = l;
        }
        __syncthreads();
#pragma unroll
        for (int ks = 0; ks < 2; ks++) {
            int kb = ks*16 + qc2;
            uint32_t a_hi[2][4], a_lo[2][4];
#pragma unroll
            for (int m = 0; m < 2; m++) {
                int r = wr + m*16 + qr;
                a_hi[m][0] = *(const uint32_t*)&Ahi[r][kb];
                a_hi[m][1] = *(const uint32_t*)&Ahi[r+8][kb];
                a_hi[m][2] = *(const uint32_t*)&Ahi[r][kb+8];
                a_hi[m][3] = *(const uint32_t*)&Ahi[r+8][kb+8];
                a_lo[m][0] = *(const uint32_t*)&Alo[r][kb];
                a_lo[m][1] = *(const uint32_t*)&Alo[r+8][kb];
                a_lo[m][2] = *(const uint32_t*)&Alo[r][kb+8];
                a_lo[m][3] = *(const uint32_t*)&Alo[r+8][kb+8];
            }
#pragma unroll
            for (int nf = 0; nf < 4; nf++) {
                int cn = wc + nf*8 + qr;
                uint32_t b_hi[2], b_lo[2];
                b_hi[0] = *(const uint32_t*)&Bshi[cn][kb];
                b_hi[1] = *(const uint32_t*)&Bshi[cn][kb+8];
                b_lo[0] = *(const uint32_t*)&Bslo[cn][kb];
                b_lo[1] = *(const uint32_t*)&Bslo[cn][kb+8];
#pragma unroll
                for (int m = 0; m < 2; m++) {
                    mma_bf16(acc[m][nf], a_hi[m], b_hi);
                    mma_bf16(acc[m][nf], a_hi[m], b_lo);
                    mma_bf16(acc[m][nf], a_lo[m], b_hi);
                }
            }
        }
        __syncthreads();
    }

    // epilogue: + bias, * scale, split to hi/lo bf16, store head-major
    int h = blockIdx.y;
#pragma unroll
    for (int m = 0; m < 2; m++) {
        int r0g = row0 + wr + m*16 + qr;
#pragma unroll
        for (int nf = 0; nf < 4; nf++) {
            int d = wc + nf*8 + qc2;
            int gc = col0 + d;
            float b0v = bias[gc], b1v = bias[gc+1];
#pragma unroll
            for (int e = 0; e < 2; e++) {
                int rg = r0g + e*8;
                int bb = rg >> 11, sq = rg & 2047;
                size_t o = ((size_t)((bb*Hh + h)*2048 + sq))*64 + d;
                float v0 = (acc[m][nf][e*2+0] + b0v) * scale;
                float v1 = (acc[m][nf][e*2+1] + b1v) * scale;
                __nv_bfloat16 h0, l0, h1, l1;
                split2(v0, h0, l0); split2(v1, h1, l1);
                __nv_bfloat162 th; th.x = h0; th.y = h1;
                __nv_bfloat162 tl; tl.x = l0; tl.y = l1;
                *(__nv_bfloat162*)&Ohi[o] = th;
                *(__nv_bfloat162*)&Olo[o] = tl;
            }
        }
    }
}

// ---------------- K2: attention (scores, exp, rowsum, AV, unnormalized attn) ----------------
// grid: (16, 32)  block: 256.  CTA = (b,h) x 128 query rows; loops M in chunks of 64.
// Masks are 32-bit words (int32 0/1 or float32 0.0/1.0): nonzero => masked.
__global__ __launch_bounds__(256) void attn_kernel(
    const float* __restrict__ kw, const int* __restrict__ kmask,
    const float* __restrict__ af, const int* __restrict__ amask,
    float* __restrict__ out_hidden, float* __restrict__ out_attn)
{
    __shared__ __nv_bfloat16 Khi[64][72], Klo[64][72];  // [m][dh]
    __shared__ __nv_bfloat16 Vhi[64][72], Vlo[64][72];  // [m][dh]
    __shared__ float s_kw[64];
    __shared__ int   s_km[64];

    int tid = threadIdx.x, lane = tid & 31, warp = tid >> 5;
    int bh = blockIdx.y, b = bh >> 3, h = bh & 7;
    int n0 = blockIdx.x * 128;
    int wrow = warp * 16;
    int qr = lane >> 2, qc2 = (lane & 3) * 2;

    // preload Q fragments (hi/lo) for this warp's 16 rows, all 64 dh
    uint32_t q_hi[4][4], q_lo[4][4];
    {
        const __nv_bfloat16* qh = g_qhi + ((size_t)bh*Nn + n0 + wrow)*64;
        const __nv_bfloat16* ql = g_qlo + ((size_t)bh*Nn + n0 + wrow)*64;
#pragma unroll
        for (int ks = 0; ks < 4; ks++) {
            int kb = ks*16 + qc2;
            q_hi[ks][0] = *(const uint32_t*)&qh[(size_t)qr*64 + kb];
            q_hi[ks][1] = *(const uint32_t*)&qh[(size_t)(qr+8)*64 + kb];
            q_hi[ks][2] = *(const uint32_t*)&qh[(size_t)qr*64 + kb + 8];
            q_hi[ks][3] = *(const uint32_t*)&qh[(size_t)(qr+8)*64 + kb + 8];
            q_lo[ks][0] = *(const uint32_t*)&ql[(size_t)qr*64 + kb];
            q_lo[ks][1] = *(const uint32_t*)&ql[(size_t)(qr+8)*64 + kb];
            q_lo[ks][2] = *(const uint32_t*)&ql[(size_t)qr*64 + kb + 8];
            q_lo[ks][3] = *(const uint32_t*)&ql[(size_t)(qr+8)*64 + kb + 8];
        }
    }

    float hid[8][4];
#pragma unroll
    for (int nf = 0; nf < 8; nf++)
#pragma unroll
        for (int e = 0; e < 4; e++) hid[nf][e] = 0.0f;
    float rs_lo = 0.0f, rs_hi = 0.0f;

    int n_lo = n0 + wrow + qr;
    size_t af_lo_row = ((size_t)b*Nn + n_lo)*Mm;
    size_t af_hi_row = ((size_t)b*Nn + n_lo + 8)*Mm;
    size_t at_lo_row = ((size_t)bh*Nn + n_lo)*Mm;
    size_t at_hi_row = ((size_t)bh*Nn + n_lo + 8)*Mm;

    for (int m0 = 0; m0 < Mm; m0 += 64) {
        __syncthreads();
        // stage K/V chunk (64 x 64, hi/lo)
        {
            const __nv_bfloat16* kh = g_khi + ((size_t)bh*Mm + m0)*64;
            const __nv_bfloat16* kl = g_klo + ((size_t)bh*Mm + m0)*64;
            const __nv_bfloat16* vh = g_vhi + ((size_t)bh*Mm + m0)*64;
            const __nv_bfloat16* vl = g_vlo + ((size_t)bh*Mm + m0)*64;
#pragma unroll
            for (int i = tid; i < 64*16; i += 256) {
                int r = i >> 4, c4 = (i & 15) * 4;
                size_t go = (size_t)r*64 + c4;
                *(uint2*)&Khi[r][c4] = *(const uint2*)&kh[go];
                *(uint2*)&Klo[r][c4] = *(const uint2*)&kl[go];
                *(uint2*)&Vhi[r][c4] = *(const uint2*)&vh[go];
                *(uint2*)&Vlo[r][c4] = *(const uint2*)&vl[go];
            }
            if (tid < 64) {
                s_kw[tid] = kw[b*Mm + m0 + tid];
                s_km[tid] = kmask[b*Mm + m0 + tid];
            }
        }
        __syncthreads();

        // QK^T: s (16 x 64) fp32, 3-way bf16 split
        float sc[8][4];
#pragma unroll
        for (int nf = 0; nf < 8; nf++)
#pragma unroll
            for (int e = 0; e < 4; e++) sc[nf][e] = 0.0f;
#pragma unroll
        for (int ks = 0; ks < 4; ks++) {
            int kb = ks*16 + qc2;
#pragma unroll
            for (int nf = 0; nf < 8; nf++) {
                int mc = nf*8 + qr;
                uint32_t b_hi[2], b_lo[2];
                b_hi[0] = *(const uint32_t*)&Khi[mc][kb];
                b_hi[1] = *(const uint32_t*)&Khi[mc][kb+8];
                b_lo[0] = *(const uint32_t*)&Klo[mc][kb];
                b_lo[1] = *(const uint32_t*)&Klo[mc][kb+8];
                mma_bf16(sc[nf], q_hi[ks], b_hi);
                mma_bf16(sc[nf], q_hi[ks], b_lo);
                mma_bf16(sc[nf], q_lo[ks], b_hi);
            }
        }

        // epilogue: scale/mask/exp, rowsum, write unnormalized attn, pack p frags
        uint32_t pa_hi[4][4], pa_lo[4][4];
#pragma unroll
        for (int nf = 0; nf < 8; nf++) {
            int ml = nf*8 + qc2;
            float2 afl = *(const float2*)&af[af_lo_row + m0 + ml];
            float2 afh = *(const float2*)&af[af_hi_row + m0 + ml];
            int2 aml = *(const int2*)&amask[af_lo_row + m0 + ml];
            int2 amh = *(const int2*)&amask[af_hi_row + m0 + ml];
            float kw0 = s_kw[ml], kw1 = s_kw[ml+1];
            int   km0 = s_km[ml], km1 = s_km[ml+1];
            float p0 = (km0 | aml.x) ? 0.0f : __expf(sc[nf][0] * afl.x * kw0);
            float p1 = (km1 | aml.y) ? 0.0f : __expf(sc[nf][1] * afl.y * kw1);
            float p2 = (km0 | amh.x) ? 0.0f : __expf(sc[nf][2] * afh.x * kw0);
            float p3 = (km1 | amh.y) ? 0.0f : __expf(sc[nf][3] * afh.y * kw1);
            rs_lo += p0 + p1;
            rs_hi += p2 + p3;
            *(float2*)&out_attn[at_lo_row + m0 + ml] = make_float2(p0, p1);
            *(float2*)&out_attn[at_hi_row + m0 + ml] = make_float2(p2, p3);
            __nv_bfloat16 h0,l0,h1,l1,h2,l2,h3,l3;
            split2(p0,h0,l0); split2(p1,h1,l1); split2(p2,h2,l2); split2(p3,h3,l3);
            int ks = nf >> 1, hf = (nf & 1) * 2;
            pa_hi[ks][hf+0] = pk2(h0, h1);
            pa_hi[ks][hf+1] = pk2(h2, h3);
            pa_lo[ks][hf+0] = pk2(l0, l1);
            pa_lo[ks][hf+1] = pk2(l2, l3);
        }

        // AV: hidden += p @ V, 3-way split
#pragma unroll
        for (int ks = 0; ks < 4; ks++) {
            int mr = ks*16 + qc2;
#pragma unroll
            for (int nf = 0; nf < 8; nf++) {
                int dc = nf*8 + qr;
                uint32_t bv_hi[2], bv_lo[2];
                bv_hi[0] = pk2(Vhi[mr][dc],   Vhi[mr+1][dc]);
                bv_hi[1] = pk2(Vhi[mr+8][dc], Vhi[mr+9][dc]);
                bv_lo[0] = pk2(Vlo[mr][dc],   Vlo[mr+1][dc]);
                bv_lo[1] = pk2(Vlo[mr+8][dc], Vlo[mr+9][dc]);
                mma_bf16(hid[nf], pa_hi[ks], bv_hi);
                mma_bf16(hid[nf], pa_hi[ks], bv_lo);
                mma_bf16(hid[nf], pa_lo[ks], bv_hi);
            }
        }
    }

    // rowsum reduce across the quad (cols are spread over lane&3 and frags)
    rs_lo += __shfl_xor_sync(0xffffffffu, rs_lo, 1);
    rs_lo += __shfl_xor_sync(0xffffffffu, rs_lo, 2);
    rs_hi += __shfl_xor_sync(0xffffffffu, rs_hi, 1);
    rs_hi += __shfl_xor_sync(0xffffffffu, rs_hi, 2);
    float inv_lo = 1.0f / rs_lo;
    float inv_hi = 1.0f / rs_hi;
    if ((lane & 3) == 0) {
        g_inv[bh*Nn + n_lo]     = inv_lo;
        g_inv[bh*Nn + n_lo + 8] = inv_hi;
    }
    // write normalized hidden: (b, n, h*64 + d)
#pragma unroll
    for (int nf = 0; nf < 8; nf++) {
        int d = nf*8 + qc2;
        size_t o_lo = ((size_t)b*Nn + n_lo)*Cc + h*64 + d;
        size_t o_hi = ((size_t)b*Nn + n_lo + 8)*Cc + h*64 + d;
        *(float2*)&out_hidden[o_lo] = make_float2(hid[nf][0]*inv_lo, hid[nf][1]*inv_lo);
        *(float2*)&out_hidden[o_hi] = make_float2(hid[nf][2]*inv_hi, hid[nf][3]*inv_hi);
    }
}

// ---------------- K3: normalize attn in place ----------------
__global__ __launch_bounds__(256) void norm_kernel(float4* __restrict__ attn4) {
    int i = blockIdx.x * 256 + threadIdx.x;     // 33,554,432 float4s total
    float4 v = attn4[i];
    float inv = g_inv[i >> 9];                  // 512 float4 per (b,h,n) row
    v.x *= inv; v.y *= inv; v.z *= inv; v.w *= inv;
    attn4[i] = v;
}

// ---------------- launch ----------------
extern "C" void kernel_launch(void* const* d_in, const int* in_sizes, int n_in,
                              void* d_out, int out_size) {
    const float* xq    = (const float*)d_in[0];
    const float* xk    = (const float*)d_in[1];
    const float* xv    = (const float*)d_in[2];
    const float* kw    = (const float*)d_in[3];
    const int*   kmask = (const int*)d_in[4];
    const float* af    = (const float*)d_in[5];
    const int*   amask = (const int*)d_in[6];
    const float* Wq    = (const float*)d_in[7];
    const float* bq    = (const float*)d_in[8];
    const float* Wk    = (const float*)d_in[9];
    const float* bk    = (const float*)d_in[10];
    const float* Wv    = (const float*)d_in[11];
    const float* bv    = (const float*)d_in[12];

    float* out_hidden = (float*)d_out;
    float* out_attn   = out_hidden + (size_t)Bb*Nn*Cc;

    proj_kernel<<<dim3(64, 8, 3), 256>>>(xq, xk, xv, Wq, bq, Wk, bk, Wv, bv);
    attn_kernel<<<dim3(16, 32), 256>>>(kw, kmask, af, amask, out_hidden, out_attn);
    norm_kernel<<<131072, 256>>>((float4*)out_attn);
}